// round 7
// baseline (speedup 1.0000x reference)
#include <cuda_runtime.h>

// Problem constants
#define N_CB   8
#define VOCAB  1024
#define VQUART 256          // vocab entries per block
#define CDIM   16
#define BATCH  8
#define HW     1024         // 32*32
#define DCH    128          // N_CB*CDIM
#define BHW    8192         // BATCH*HW
#define NITEMS 65536        // BHW * N_CB

// Output layout (float32, concatenated flat in reference order)
#define OFF_Q      0
#define OFF_IDX    1048576
#define OFF_COMMIT 1114112
#define OFF_NCB    1114113
#define OFF_NCNT   1245185
#define OFF_NW     1253377

#define DECAY_F 0.99f
#define ALPHA_F 0.01f
#define EPS_F   1e-5f

// self-cleaning device state (zero-initialized at module load; every kernel
// restores it to zero after consuming it, so graph replays are deterministic)
__device__ unsigned long long vq_scratch[NITEMS];   // argmin: ~((key<<32)|idx); 0 == empty/worst
__device__ float cnt_scr[N_CB * VOCAB];             // raw counts
__device__ float sum_scr[N_CB * VOCAB * CDIM];      // raw z sums
__device__ float n_dev[N_CB];                       // per-cb n (overwritten each run)

// ---------- f32x2 packed helpers ----------
static __device__ __forceinline__ unsigned long long pack2(float lo, float hi) {
    unsigned long long r;
    asm("mov.b64 %0, {%1,%2};" : "=l"(r) : "f"(lo), "f"(hi));
    return r;
}
static __device__ __forceinline__ void unpack2(unsigned long long v, float& lo, float& hi) {
    asm("mov.b64 {%0,%1}, %2;" : "=f"(lo), "=f"(hi) : "l"(v));
}
static __device__ __forceinline__ unsigned long long fma2(unsigned long long a,
                                                          unsigned long long b,
                                                          unsigned long long c) {
    unsigned long long d;
    asm("fma.rn.f32x2 %0, %1, %2, %3;" : "=l"(d) : "l"(a), "l"(b), "l"(c));
    return d;
}
// monotone float -> u32 (order-preserving for all finite floats)
static __device__ __forceinline__ unsigned int fkey(float s) {
    unsigned int b = __float_as_uint(s);
    return (b & 0x80000000u) ? ~b : (b | 0x80000000u);
}

// ---------- kernel 1: distance sweep + argmin ----------
// grid: (16, 8, 4) -> x: chunk of 512 positions, y: codebook, z: vocab quarter
// block: 256 threads, 2 positions per thread (low regs -> 4 blocks/SM)
// smem per vocab v (10 u64, 80B, 16B aligned):
//   [0..7]  dim-pairs (c[2k], c[2k+1])  -- natural row order
//   [8]     (0.5*||c||^2, 0.0)          -- folded into accumulator init
//   [9]     pad
__global__ __launch_bounds__(256, 4) void vq_main(const float* __restrict__ z,
                                                  const float* __restrict__ cbs,
                                                  float* out) {
    __shared__ __align__(16) unsigned long long sm2[VQUART * 10];   // 20480 B
    float* smf = (float*)sm2;

    const int cb    = blockIdx.y;
    const int vbase = blockIdx.z * VQUART;
    const int tid   = threadIdx.x;

    // zero commitment accumulator once per replay (ordered before epi launch)
    if (blockIdx.x == 0 && blockIdx.y == 0 && blockIdx.z == 0 && tid == 0)
        out[OFF_COMMIT] = 0.0f;

    // load quarter codebook (natural layout), stride 20 floats per vocab row
    {
        const float* src = cbs + ((size_t)cb * VOCAB + vbase) * CDIM;  // 4096 floats
        #pragma unroll
        for (int t = 0; t < 16; t++) {
            int i = tid + t * 256;
            int v = i >> 4, j = i & 15;
            smf[v * 20 + j] = src[i];
        }
    }
    __syncthreads();
    // h = 0.5||c||^2 per vocab (one vocab per thread)
    {
        const int v = tid;
        const float* r = smf + v * 20;
        float s = 0.0f;
        #pragma unroll
        for (int j = 0; j < CDIM; j++) s += r[j] * r[j];
        smf[v * 20 + 16] = 0.5f * s;
        smf[v * 20 + 17] = 0.0f;
    }
    __syncthreads();

    // two positions per thread (same batch image: 512 | 1024)
    const int p0 = blockIdx.x * 512 + tid;
    const int b  = p0 >> 10;
    const int hw0 = p0 & (HW - 1);
    const int hw1 = (p0 + 256) & (HW - 1);

    const float* zb = z + (size_t)b * DCH * HW + (size_t)cb * CDIM * HW;

    unsigned long long zz0[8], zz1[8];
    #pragma unroll
    for (int k = 0; k < 8; k++) {
        const float* e = zb + (2 * k) * HW;
        const float* o = zb + (2 * k + 1) * HW;
        zz0[k] = pack2(-e[hw0], -o[hw0]);
        zz1[k] = pack2(-e[hw1], -o[hw1]);
    }

    float best0 = 3.0e38f, best1 = 3.0e38f;
    int   bi0 = 0, bi1 = 0;

    #pragma unroll 2
    for (int v = 0; v < VQUART; v++) {
        const ulonglong2* row = reinterpret_cast<const ulonglong2*>(sm2 + v * 10);
        ulonglong2 r0 = row[0], r1 = row[1], r2 = row[2], r3 = row[3];
        const unsigned long long h2 = sm2[v * 10 + 8];

        unsigned long long a0, a1;
        a0 = fma2(zz0[0], r0.x, h2); a1 = fma2(zz1[0], r0.x, h2);
        a0 = fma2(zz0[1], r0.y, a0); a1 = fma2(zz1[1], r0.y, a1);
        a0 = fma2(zz0[2], r1.x, a0); a1 = fma2(zz1[2], r1.x, a1);
        a0 = fma2(zz0[3], r1.y, a0); a1 = fma2(zz1[3], r1.y, a1);
        a0 = fma2(zz0[4], r2.x, a0); a1 = fma2(zz1[4], r2.x, a1);
        a0 = fma2(zz0[5], r2.y, a0); a1 = fma2(zz1[5], r2.y, a1);
        a0 = fma2(zz0[6], r3.x, a0); a1 = fma2(zz1[6], r3.x, a1);
        a0 = fma2(zz0[7], r3.y, a0); a1 = fma2(zz1[7], r3.y, a1);

        float lo, hi, s;
        bool t;
        unpack2(a0, lo, hi); s = lo + hi;
        t = s < best0; best0 = t ? s : best0; bi0 = t ? v : bi0;
        unpack2(a1, lo, hi); s = lo + hi;
        t = s < best1; best1 = t ? s : best1; bi1 = t ? v : bi1;
    }

    // combine across vocab quarters: atomicMax on complemented keys
    // (max of complements == complement of min; empty slot 0 == worst; ties -> smaller idx)
    unsigned long long* sc = vq_scratch + (size_t)cb * BHW;
    atomicMax(&sc[p0],
              ~(((unsigned long long)fkey(best0) << 32) | (unsigned)(vbase + bi0)));
    atomicMax(&sc[p0 + 256],
              ~(((unsigned long long)fkey(best1) << 32) | (unsigned)(vbase + bi1)));
}

// ---------- kernel 2: epilogue (quantize, indices, scatter, commitment, n) ----------
// grid: (32, 8), block 256, one position per thread
__global__ __launch_bounds__(256) void vq_epi(const float* __restrict__ z,
                                              const float* __restrict__ cbs,
                                              const float* __restrict__ ema_count,
                                              float* out) {
    const int cb  = blockIdx.y;
    const int tid = threadIdx.x;
    const int pos = blockIdx.x * 256 + tid;
    const int b   = pos >> 10;
    const int hw  = pos & (HW - 1);

    // read winner, self-clean the slot
    unsigned long long* scp = vq_scratch + (size_t)cb * BHW + pos;
    const unsigned long long comp = *scp;
    *scp = 0ull;
    const int bi = (int)(unsigned)(~comp);

    const float* crow = cbs + ((size_t)cb * VOCAB + bi) * CDIM;
    const float* zb   = z + (size_t)b * DCH * HW + (size_t)cb * CDIM * HW + hw;

    float* qout = out + OFF_Q + (size_t)b * DCH * HW + (size_t)cb * CDIM * HW + hw;
    float* wdst = sum_scr + ((size_t)cb * VOCAB + bi) * CDIM;

    float locc = 0.0f;
    #pragma unroll
    for (int j = 0; j < CDIM; j++) {
        const float zj = zb[(size_t)j * HW];
        const float cj = crow[j];
        qout[(size_t)j * HW] = zj + (cj - zj);       // match zq_st rounding
        const float d = zj - cj;
        locc += d * d;
        atomicAdd(&wdst[j], zj);                     // raw sums (scaled in vq_final)
    }
    out[OFF_IDX + (size_t)b * (N_CB * HW) + (size_t)cb * HW + hw] = (float)bi;
    atomicAdd(&cnt_scr[cb * VOCAB + bi], 1.0f);      // raw counts

    // commitment: shuffle reduce -> 1 atomic per block
    #pragma unroll
    for (int st = 16; st > 0; st >>= 1)
        locc += __shfl_xor_sync(0xFFFFFFFFu, locc, st);
    __shared__ float red[8];
    if ((tid & 31) == 0) red[tid >> 5] = locc;
    __syncthreads();
    if (tid == 0) {
        float s = 0.0f;
        #pragma unroll
        for (int w = 0; w < 8; w++) s += red[w];
        atomicAdd(out + OFF_COMMIT, s * (1.0f / (float)(BHW * N_CB * CDIM)));
    }

    // blocks with x==0 also compute n[cb] = 0.99*sum(ema_count[cb]) + 0.01*BHW
    if (blockIdx.x == 0) {
        float s = ema_count[cb * VOCAB + tid] + ema_count[cb * VOCAB + tid + 256]
                + ema_count[cb * VOCAB + tid + 512] + ema_count[cb * VOCAB + tid + 768];
        #pragma unroll
        for (int st = 16; st > 0; st >>= 1)
            s += __shfl_xor_sync(0xFFFFFFFFu, s, st);
        __shared__ float nred[8];
        if ((tid & 31) == 0) nred[tid >> 5] = s;
        __syncthreads();
        if (tid == 0) {
            float t = 0.0f;
            #pragma unroll
            for (int w = 0; w < 8; w++) t += nred[w];
            n_dev[cb] = DECAY_F * t + ALPHA_F * (float)BHW;
        }
    }
}

// ---------- kernel 3: EMA blend + normalized codebook update ----------
// grid 512 x 256, one weight element per thread
__global__ __launch_bounds__(256) void vq_final(const float* __restrict__ ema_count,
                                                const float* __restrict__ ema_weight,
                                                float* out) {
    const int i  = blockIdx.x * 256 + threadIdx.x;    // 0 .. 131071
    const int cb = i >> 14;
    const int v  = (i >> 4) & (VOCAB - 1);
    const int j  = i & 15;

    const float sums = sum_scr[i];
    sum_scr[i] = 0.0f;                                // self-clean
    const float nw = DECAY_F * ema_weight[i] + ALPHA_F * sums;
    out[OFF_NW + i] = nw;

    const float craw = cnt_scr[cb * VOCAB + v];
    __syncwarp();                                     // all 16 readers done before clean
    if (j == 0) cnt_scr[cb * VOCAB + v] = 0.0f;       // self-clean

    const float ncnt = DECAY_F * ema_count[cb * VOCAB + v] + ALPHA_F * craw;
    if (j == 0) out[OFF_NCNT + cb * VOCAB + v] = ncnt;

    const float n = n_dev[cb];
    const float countv = (ncnt + EPS_F) / (n + VOCAB * EPS_F) * n;
    out[OFF_NCB + i] = __fdividef(nw, countv);
}

extern "C" void kernel_launch(void* const* d_in, const int* in_sizes, int n_in,
                              void* d_out, int out_size) {
    const float* z   = (const float*)d_in[0];
    const float* cbs = (const float*)d_in[1];
    const float* ec  = (const float*)d_in[2];
    const float* ew  = (const float*)d_in[3];
    float* out = (float*)d_out;

    dim3 gmain(16, N_CB, 4);
    vq_main<<<gmain, 256>>>(z, cbs, out);
    dim3 gepi(32, N_CB);
    vq_epi<<<gepi, 256>>>(z, cbs, ec, out);
    vq_final<<<512, 256>>>(ec, ew, out);
}

// round 8
// speedup vs baseline: 1.8276x; 1.8276x over previous
#include <cuda_runtime.h>

// Problem constants
#define N_CB   8
#define VOCAB  1024
#define VSLICE 128          // vocab entries per block (8-way split)
#define CDIM   16
#define BATCH  8
#define HW     1024         // 32*32
#define DCH    128          // N_CB*CDIM
#define BHW    8192         // BATCH*HW
#define NITEMS 65536        // BHW * N_CB

// Output layout (float32, concatenated flat in reference order)
#define OFF_Q      0
#define OFF_IDX    1048576
#define OFF_COMMIT 1114112
#define OFF_NCB    1114113
#define OFF_NCNT   1245185
#define OFF_NW     1253377

#define DECAY_F 0.99f
#define ALPHA_F 0.01f
#define EPS_F   1e-5f

// self-cleaning device state (zero-initialized at module load; every kernel
// restores it to zero after consuming it, so graph replays are deterministic)
__device__ unsigned long long vq_scratch[NITEMS];   // argmin: ~((key<<32)|idx); 0 == empty/worst
__device__ float cnt_scr[N_CB * VOCAB];             // raw counts
__device__ float sum_scr[N_CB * VOCAB * CDIM];      // raw z sums
__device__ float n_dev[N_CB];                       // per-cb n (overwritten each run)

// ---------- f32x2 packed helpers ----------
static __device__ __forceinline__ unsigned long long pack2(float lo, float hi) {
    unsigned long long r;
    asm("mov.b64 %0, {%1,%2};" : "=l"(r) : "f"(lo), "f"(hi));
    return r;
}
static __device__ __forceinline__ void unpack2(unsigned long long v, float& lo, float& hi) {
    asm("mov.b64 {%0,%1}, %2;" : "=f"(lo), "=f"(hi) : "l"(v));
}
static __device__ __forceinline__ unsigned long long fma2(unsigned long long a,
                                                          unsigned long long b,
                                                          unsigned long long c) {
    unsigned long long d;
    asm("fma.rn.f32x2 %0, %1, %2, %3;" : "=l"(d) : "l"(a), "l"(b), "l"(c));
    return d;
}
// monotone float -> u32 (order-preserving for all finite floats)
static __device__ __forceinline__ unsigned int fkey(float s) {
    unsigned int b = __float_as_uint(s);
    return (b & 0x80000000u) ? ~b : (b | 0x80000000u);
}

// ---------- kernel 1: distance sweep + argmin ----------
// grid: (16, 8, 8) -> x: chunk of 512 positions, y: codebook, z: vocab slice
// block: 128 threads, 4 positions per thread (high ILP: 4 independent chains)
// smem per vocab v (10 u64, 80B, 16B aligned):
//   [0..7]  dim-pairs (c[2k], c[2k+1])  -- natural row order
//   [8]     (0.5*||c||^2, 0.0)          -- folded into accumulator init
//   [9]     pad
__global__ __launch_bounds__(128, 4) void vq_main(const float* __restrict__ z,
                                                  const float* __restrict__ cbs,
                                                  float* out) {
    __shared__ __align__(16) unsigned long long sm2[VSLICE * 10];   // 10240 B
    float* smf = (float*)sm2;

    const int cb    = blockIdx.y;
    const int vbase = blockIdx.z * VSLICE;
    const int tid   = threadIdx.x;

    // zero commitment accumulator once per replay (epi launches after main completes)
    if (blockIdx.x == 0 && blockIdx.y == 0 && blockIdx.z == 0 && tid == 0)
        out[OFF_COMMIT] = 0.0f;

    // load slice codebook (natural layout), stride 20 floats per vocab row
    {
        const float* src = cbs + ((size_t)cb * VOCAB + vbase) * CDIM;  // 2048 floats
        #pragma unroll
        for (int t = 0; t < 16; t++) {
            int i = tid + t * 128;
            int v = i >> 4, j = i & 15;
            smf[v * 20 + j] = src[i];
        }
    }
    __syncthreads();
    // h = 0.5||c||^2 per vocab (one vocab per thread, tid<128 covers VSLICE=128)
    {
        const int v = tid;
        const float* r = smf + v * 20;
        float s = 0.0f;
        #pragma unroll
        for (int j = 0; j < CDIM; j++) s += r[j] * r[j];
        smf[v * 20 + 16] = 0.5f * s;
        smf[v * 20 + 17] = 0.0f;
    }
    __syncthreads();

    // four positions per thread (all within the same batch image)
    const int p0 = blockIdx.x * 512 + tid;
    const int b  = p0 >> 10;
    const int hw0 = p0 & (HW - 1);
    const int hw1 = (p0 + 128) & (HW - 1);
    const int hw2 = (p0 + 256) & (HW - 1);
    const int hw3 = (p0 + 384) & (HW - 1);

    const float* zb = z + (size_t)b * DCH * HW + (size_t)cb * CDIM * HW;

    unsigned long long zz0[8], zz1[8], zz2[8], zz3[8];
    #pragma unroll
    for (int k = 0; k < 8; k++) {
        const float* e = zb + (2 * k) * HW;
        const float* o = zb + (2 * k + 1) * HW;
        zz0[k] = pack2(-e[hw0], -o[hw0]);
        zz1[k] = pack2(-e[hw1], -o[hw1]);
        zz2[k] = pack2(-e[hw2], -o[hw2]);
        zz3[k] = pack2(-e[hw3], -o[hw3]);
    }

    float best0 = 3.0e38f, best1 = 3.0e38f, best2 = 3.0e38f, best3 = 3.0e38f;
    int   bi0 = 0, bi1 = 0, bi2 = 0, bi3 = 0;

    #pragma unroll 2
    for (int v = 0; v < VSLICE; v++) {
        const ulonglong2* row = reinterpret_cast<const ulonglong2*>(sm2 + v * 10);
        ulonglong2 r0 = row[0], r1 = row[1], r2 = row[2], r3 = row[3];
        const unsigned long long h2 = sm2[v * 10 + 8];

        unsigned long long a0, a1, a2, a3;
        a0 = fma2(zz0[0], r0.x, h2); a1 = fma2(zz1[0], r0.x, h2);
        a2 = fma2(zz2[0], r0.x, h2); a3 = fma2(zz3[0], r0.x, h2);
        a0 = fma2(zz0[1], r0.y, a0); a1 = fma2(zz1[1], r0.y, a1);
        a2 = fma2(zz2[1], r0.y, a2); a3 = fma2(zz3[1], r0.y, a3);
        a0 = fma2(zz0[2], r1.x, a0); a1 = fma2(zz1[2], r1.x, a1);
        a2 = fma2(zz2[2], r1.x, a2); a3 = fma2(zz3[2], r1.x, a3);
        a0 = fma2(zz0[3], r1.y, a0); a1 = fma2(zz1[3], r1.y, a1);
        a2 = fma2(zz2[3], r1.y, a2); a3 = fma2(zz3[3], r1.y, a3);
        a0 = fma2(zz0[4], r2.x, a0); a1 = fma2(zz1[4], r2.x, a1);
        a2 = fma2(zz2[4], r2.x, a2); a3 = fma2(zz3[4], r2.x, a3);
        a0 = fma2(zz0[5], r2.y, a0); a1 = fma2(zz1[5], r2.y, a1);
        a2 = fma2(zz2[5], r2.y, a2); a3 = fma2(zz3[5], r2.y, a3);
        a0 = fma2(zz0[6], r3.x, a0); a1 = fma2(zz1[6], r3.x, a1);
        a2 = fma2(zz2[6], r3.x, a2); a3 = fma2(zz3[6], r3.x, a3);
        a0 = fma2(zz0[7], r3.y, a0); a1 = fma2(zz1[7], r3.y, a1);
        a2 = fma2(zz2[7], r3.y, a2); a3 = fma2(zz3[7], r3.y, a3);

        float lo, hi, s;
        bool t;
        unpack2(a0, lo, hi); s = lo + hi;
        t = s < best0; best0 = t ? s : best0; bi0 = t ? v : bi0;
        unpack2(a1, lo, hi); s = lo + hi;
        t = s < best1; best1 = t ? s : best1; bi1 = t ? v : bi1;
        unpack2(a2, lo, hi); s = lo + hi;
        t = s < best2; best2 = t ? s : best2; bi2 = t ? v : bi2;
        unpack2(a3, lo, hi); s = lo + hi;
        t = s < best3; best3 = t ? s : best3; bi3 = t ? v : bi3;
    }

    // combine across vocab slices: atomicMax on complemented keys
    // (max of complements == complement of min; empty slot 0 == worst; ties -> smaller idx)
    unsigned long long* sc = vq_scratch + (size_t)cb * BHW;
    atomicMax(&sc[p0],
              ~(((unsigned long long)fkey(best0) << 32) | (unsigned)(vbase + bi0)));
    atomicMax(&sc[p0 + 128],
              ~(((unsigned long long)fkey(best1) << 32) | (unsigned)(vbase + bi1)));
    atomicMax(&sc[p0 + 256],
              ~(((unsigned long long)fkey(best2) << 32) | (unsigned)(vbase + bi2)));
    atomicMax(&sc[p0 + 384],
              ~(((unsigned long long)fkey(best3) << 32) | (unsigned)(vbase + bi3)));
}

// ---------- kernel 2: epilogue (quantize, indices, scatter, commitment, n) ----------
// grid: (64, 8), block 128, one position per thread
__global__ __launch_bounds__(128) void vq_epi(const float* __restrict__ z,
                                              const float* __restrict__ cbs,
                                              const float* __restrict__ ema_count,
                                              float* out) {
    const int cb  = blockIdx.y;
    const int tid = threadIdx.x;
    const int pos = blockIdx.x * 128 + tid;
    const int b   = pos >> 10;
    const int hw  = pos & (HW - 1);

    // read winner, self-clean the slot
    unsigned long long* scp = vq_scratch + (size_t)cb * BHW + pos;
    const unsigned long long comp = *scp;
    *scp = 0ull;
    const int bi = (int)(unsigned)(~comp);

    const float* crow = cbs + ((size_t)cb * VOCAB + bi) * CDIM;
    const float* zb   = z + (size_t)b * DCH * HW + (size_t)cb * CDIM * HW + hw;

    float* qout = out + OFF_Q + (size_t)b * DCH * HW + (size_t)cb * CDIM * HW + hw;
    float* wdst = sum_scr + ((size_t)cb * VOCAB + bi) * CDIM;

    float locc = 0.0f;
    #pragma unroll
    for (int j = 0; j < CDIM; j++) {
        const float zj = zb[(size_t)j * HW];
        const float cj = crow[j];
        qout[(size_t)j * HW] = zj + (cj - zj);       // match zq_st rounding
        const float d = zj - cj;
        locc += d * d;
        atomicAdd(&wdst[j], zj);                     // raw sums (scaled in vq_final)
    }
    out[OFF_IDX + (size_t)b * (N_CB * HW) + (size_t)cb * HW + hw] = (float)bi;
    atomicAdd(&cnt_scr[cb * VOCAB + bi], 1.0f);      // raw counts

    // commitment: shuffle reduce -> 1 atomic per block
    #pragma unroll
    for (int st = 16; st > 0; st >>= 1)
        locc += __shfl_xor_sync(0xFFFFFFFFu, locc, st);
    __shared__ float red[4];
    if ((tid & 31) == 0) red[tid >> 5] = locc;
    __syncthreads();
    if (tid == 0)
        atomicAdd(out + OFF_COMMIT,
                  (red[0] + red[1] + red[2] + red[3]) * (1.0f / (float)(BHW * N_CB * CDIM)));

    // blocks with x==0 also compute n[cb] = 0.99*sum(ema_count[cb]) + 0.01*BHW
    if (blockIdx.x == 0) {
        float s = 0.0f;
        #pragma unroll
        for (int t = 0; t < 8; t++) s += ema_count[cb * VOCAB + tid + t * 128];
        #pragma unroll
        for (int st = 16; st > 0; st >>= 1)
            s += __shfl_xor_sync(0xFFFFFFFFu, s, st);
        __shared__ float nred[4];
        if ((tid & 31) == 0) nred[tid >> 5] = s;
        __syncthreads();
        if (tid == 0)
            n_dev[cb] = DECAY_F * (nred[0] + nred[1] + nred[2] + nred[3])
                      + ALPHA_F * (float)BHW;
    }
}

// ---------- kernel 3: EMA blend + normalized codebook update ----------
// grid 512 x 256, one weight element per thread
__global__ __launch_bounds__(256) void vq_final(const float* __restrict__ ema_count,
                                                const float* __restrict__ ema_weight,
                                                float* out) {
    const int i  = blockIdx.x * 256 + threadIdx.x;    // 0 .. 131071
    const int cb = i >> 14;
    const int v  = (i >> 4) & (VOCAB - 1);
    const int j  = i & 15;

    const float sums = sum_scr[i];
    sum_scr[i] = 0.0f;                                // self-clean
    const float nw = DECAY_F * ema_weight[i] + ALPHA_F * sums;
    out[OFF_NW + i] = nw;

    const float craw = cnt_scr[cb * VOCAB + v];
    __syncwarp();                                     // all 16 readers done before clean
    if (j == 0) cnt_scr[cb * VOCAB + v] = 0.0f;       // self-clean

    const float ncnt = DECAY_F * ema_count[cb * VOCAB + v] + ALPHA_F * craw;
    if (j == 0) out[OFF_NCNT + cb * VOCAB + v] = ncnt;

    const float n = n_dev[cb];
    const float countv = (ncnt + EPS_F) / (n + VOCAB * EPS_F) * n;
    out[OFF_NCB + i] = __fdividef(nw, countv);
}

extern "C" void kernel_launch(void* const* d_in, const int* in_sizes, int n_in,
                              void* d_out, int out_size) {
    const float* z   = (const float*)d_in[0];
    const float* cbs = (const float*)d_in[1];
    const float* ec  = (const float*)d_in[2];
    const float* ew  = (const float*)d_in[3];
    float* out = (float*)d_out;

    dim3 gmain(16, N_CB, 8);
    vq_main<<<gmain, 128>>>(z, cbs, out);
    dim3 gepi(64, N_CB);
    vq_epi<<<gepi, 128>>>(z, cbs, ec, out);
    vq_final<<<512, 256>>>(ec, ew, out);
}